// round 1
// baseline (speedup 1.0000x reference)
#include <cuda_runtime.h>
#include <cstdint>

#define B_  8
#define N_  2048
#define D_  1024
#define E_  64
#define CAP_ 64
#define TOK_ (B_*N_)                 // 16384
#define DTOT_ ((long long)TOK_*E_*CAP_) // 67108864

// -------- scratch (device globals; no allocation allowed) --------
__device__ float d_g1[TOK_], d_g2[TOK_];
__device__ int   d_i1[TOK_], d_i2[TOK_];
__device__ int   d_pos1[TOK_], d_pos2[TOK_];
__device__ int   d_keep1[TOK_], d_keep2[TOK_];
__device__ float d_sumg[B_*E_];
__device__ int   d_cnt1[B_*E_];

// -------- K0: zero the small reduction buffers (graph-replay safe) --------
__global__ void k0_zero() {
    int i = blockIdx.x * blockDim.x + threadIdx.x;
    if (i < B_*E_) { d_sumg[i] = 0.0f; d_cnt1[i] = 0; }
}

// -------- K1: GEMM (x@W) + softmax + top2 + gates + loss partials --------
#define TPB1 128
#define KC   64
__global__ __launch_bounds__(TPB1) void k1_gate(const float* __restrict__ x,
                                                const float* __restrict__ W) {
    __shared__ float sx[TPB1][KC + 1];   // +1 pad -> conflict-free row reads
    __shared__ float sw[KC][E_];

    const int tid  = threadIdx.x;
    const int tok0 = blockIdx.x * TPB1;
    const int tok  = tok0 + tid;

    float acc[E_];
#pragma unroll
    for (int e = 0; e < E_; e++) acc[e] = 0.0f;

    for (int kc = 0; kc < D_; kc += KC) {
        // W chunk: KC*E_ = 4096 floats = 1024 float4, 8 per thread (coalesced)
        {
            const float4* wg = (const float4*)(W + kc * E_);
            float4* ws = (float4*)&sw[0][0];
#pragma unroll
            for (int i = 0; i < (KC*E_/4)/TPB1; i++)
                ws[tid + i*TPB1] = wg[tid + i*TPB1];
        }
        // x chunk: TPB1 rows x KC floats; coalesced float4 loads, scalar smem stores
        {
#pragma unroll
            for (int i = 0; i < (TPB1*KC/4)/TPB1; i++) {
                int f = tid + i*TPB1;
                int r = f / (KC/4);
                int c = f % (KC/4);
                float4 v = *(const float4*)(x + (size_t)(tok0 + r)*D_ + kc + c*4);
                float* dst = &sx[r][c*4];
                dst[0]=v.x; dst[1]=v.y; dst[2]=v.z; dst[3]=v.w;
            }
        }
        __syncthreads();
#pragma unroll 4
        for (int kk = 0; kk < KC; kk++) {
            float xv = sx[tid][kk];
            const float4* wr = (const float4*)&sw[kk][0];   // broadcast LDS.128
#pragma unroll
            for (int e4 = 0; e4 < E_/4; e4++) {
                float4 w = wr[e4];
                acc[e4*4+0] += xv * w.x;
                acc[e4*4+1] += xv * w.y;
                acc[e4*4+2] += xv * w.z;
                acc[e4*4+3] += xv * w.w;
            }
        }
        __syncthreads();
    }

    // ---- top-1 / top-2 on logits (monotonic under softmax; first-occurrence ties) ----
    float m1 = -1e30f; int i1 = 0;
#pragma unroll
    for (int e = 0; e < E_; e++)
        if (acc[e] > m1) { m1 = acc[e]; i1 = e; }
    float m2 = -1e30f; int i2 = 0;
#pragma unroll
    for (int e = 0; e < E_; e++)
        if (e != i1 && acc[e] > m2) { m2 = acc[e]; i2 = e; }

    // ---- softmax (exp w.r.t. max; p1 = 1/Z, p2 = exp(m2-m1)/Z) ----
    float Z = 0.0f;
#pragma unroll
    for (int e = 0; e < E_; e++) { acc[e] = __expf(acc[e] - m1); Z += acc[e]; }
    float invZ = 1.0f / Z;
    float e2v  = __expf(m2 - m1);

    // gate normalization: g = p/(p1+p2+eps); with p1=1/Z, p2=e2v/Z:
    float den = 1.0f + e2v + 1e-9f * Z;
    float g1  = 1.0f / den;
    float g2  = e2v / den;
    int keep2 = (g2 > 0.2f) ? 1 : 0;   // THRESHOLD policy

    d_g1[tok] = g1;  d_g2[tok] = g2;
    d_i1[tok] = i1;  d_i2[tok] = i2;
    d_keep2[tok] = keep2;

    const int b = tok >> 11;   // tok / N_
    atomicAdd(&d_cnt1[b*E_ + i1], 1);

    // loss partial: sum over tokens of softmax prob per expert (warp-reduce then atomic)
#pragma unroll
    for (int e = 0; e < E_; e++) {
        float v = acc[e] * invZ;
        v += __shfl_xor_sync(0xffffffffu, v, 16);
        v += __shfl_xor_sync(0xffffffffu, v, 8);
        v += __shfl_xor_sync(0xffffffffu, v, 4);
        v += __shfl_xor_sync(0xffffffffu, v, 2);
        v += __shfl_xor_sync(0xffffffffu, v, 1);
        if ((tid & 31) == 0) atomicAdd(&d_sumg[b*E_ + e], v);
    }
}

// -------- K2: capacity scan (warp-parallel prefix counting per batch) --------
__global__ __launch_bounds__(32) void k2_scan() {
    const int b    = blockIdx.x;
    const int lane = threadIdx.x;
    __shared__ int s_cnt[E_];
    __shared__ int s_m1[E_];

    s_cnt[lane] = 0; s_cnt[lane + 32] = 0;
    __syncwarp();

    const int base = b * N_;

    // pass 1: top-1 positions (exclusive running count per expert)
    for (int c = 0; c < N_/32; c++) {
        int t  = base + c*32 + lane;
        int i1 = d_i1[t];
        unsigned grp = __match_any_sync(0xffffffffu, i1);
        int before = __popc(grp & ((1u << lane) - 1u));
        int cnt = s_cnt[i1];
        __syncwarp();
        int pos = cnt + before;
        d_pos1[t]  = pos;
        d_keep1[t] = (pos < CAP_) ? 1 : 0;
        int leader = __ffs(grp) - 1;
        if (lane == leader) s_cnt[i1] = cnt + __popc(grp);
        __syncwarp();
    }

    // mask_1_count = min(total top1 count, CAP); reset counters for pass 2
    s_m1[lane]      = min(s_cnt[lane], CAP_);
    s_m1[lane + 32] = min(s_cnt[lane + 32], CAP_);
    __syncwarp();
    s_cnt[lane] = 0; s_cnt[lane + 32] = 0;
    __syncwarp();

    // pass 2: top-2 positions among threshold-passing tokens, offset by mask_1_count
    for (int c = 0; c < N_/32; c++) {
        int t  = base + c*32 + lane;
        int i2 = d_i2[t];
        int kp = d_keep2[t];
        unsigned kmask = __ballot_sync(0xffffffffu, kp);
        unsigned grp   = __match_any_sync(0xffffffffu, i2) & kmask;
        int before = __popc(grp & ((1u << lane) - 1u));
        int cnt = s_cnt[i2];
        int m1v = s_m1[i2];
        __syncwarp();
        if (kp) {
            int pos = cnt + before + m1v;
            d_pos2[t]  = pos;
            d_keep2[t] = (pos < CAP_) ? 1 : 0;
            int leader = __ffs(grp) - 1;
            if (lane == leader) s_cnt[i2] = cnt + __popc(grp);
        }
        __syncwarp();
    }
}

// -------- K3: single-pass output fill: one warp per token zeroes its 2x16KB
//          plane (float4 stores) and scatters its <=2 nonzeros --------
__global__ __launch_bounds__(256) void k3_fill(float* __restrict__ out) {
    const int gwarp = (blockIdx.x * blockDim.x + threadIdx.x) >> 5;  // = token
    const int lane  = threadIdx.x & 31;

    const long long baseD = (long long)gwarp * (E_ * CAP_);
    float4 z = make_float4(0.f, 0.f, 0.f, 0.f);
    float4* pd = (float4*)(out + baseD);           // dispatch plane
    float4* pc = (float4*)(out + DTOT_ + baseD);   // combine plane
#pragma unroll
    for (int i = 0; i < 32; i++) {
        pd[lane + i*32] = z;
        pc[lane + i*32] = z;
    }
    __syncwarp();   // memory-ordering among warp lanes before scatter
    if (lane == 0) {
        if (d_keep1[gwarp]) {
            int t = d_i1[gwarp]*CAP_ + d_pos1[gwarp];
            out[baseD + t]         = 1.0f;
            out[DTOT_ + baseD + t] = d_g1[gwarp];
        }
        if (d_keep2[gwarp]) {
            int t = d_i2[gwarp]*CAP_ + d_pos2[gwarp];
            out[baseD + t]         = 1.0f;
            out[DTOT_ + baseD + t] = d_g2[gwarp];
        }
    }
}

// -------- K4: loss finalize --------
__global__ __launch_bounds__(512) void k4_loss(float* __restrict__ out, long long out_size) {
    __shared__ float red[16];
    const int i = threadIdx.x;          // 512 = B_*E_
    float v = d_sumg[i] * (float)d_cnt1[i];
    v += __shfl_xor_sync(0xffffffffu, v, 16);
    v += __shfl_xor_sync(0xffffffffu, v, 8);
    v += __shfl_xor_sync(0xffffffffu, v, 4);
    v += __shfl_xor_sync(0xffffffffu, v, 2);
    v += __shfl_xor_sync(0xffffffffu, v, 1);
    if ((i & 31) == 0) red[i >> 5] = v;
    __syncthreads();
    if (i == 0) {
        float s = 0.0f;
        for (int w = 0; w < 16; w++) s += red[w];
        // loss = mean(proxy_m * density_1) * E^2
        //      = sum(sumg*cnt) / (n*n) * E^2 / (B*E) = sum * 8 / n^2
        float loss = s * (8.0f / ((float)N_ * (float)N_));
        if (out_size > 2*DTOT_) out[2*DTOT_] = loss;
    }
}

extern "C" void kernel_launch(void* const* d_in, const int* in_sizes, int n_in,
                              void* d_out, int out_size) {
    const float* x = (const float*)d_in[0];
    const float* W = (const float*)d_in[1];
    float* out = (float*)d_out;

    k0_zero<<<1, 512>>>();
    k1_gate<<<TOK_/TPB1, TPB1>>>(x, W);          // 128 blocks x 128 threads
    k2_scan<<<B_, 32>>>();                       // 8 warps, one per batch
    k3_fill<<<TOK_*32/256, 256>>>(out);          // 2048 blocks, 1 warp/token
    k4_loss<<<1, 512>>>(out, (long long)out_size);
}

// round 2
// speedup vs baseline: 1.1203x; 1.1203x over previous
#include <cuda_runtime.h>
#include <cstdint>

#define B_  8
#define N_  2048
#define D_  1024
#define E_  64
#define CAP_ 64
#define TOK_ (B_*N_)                     // 16384
#define DTOT_ ((long long)TOK_*E_*CAP_)  // 67108864

// -------- scratch (device globals; no allocation allowed) --------
__device__ float d_g1[TOK_], d_g2[TOK_];
__device__ int   d_i1[TOK_], d_i2[TOK_];
__device__ int   d_pos1[TOK_], d_pos2[TOK_];
__device__ int   d_keep1[TOK_], d_keep2[TOK_];
__device__ float d_sumg[B_*E_];
__device__ int   d_cnt1[B_*E_];

// -------- packed f32x2 helpers --------
__device__ __forceinline__ unsigned long long pk2(float v) {
    unsigned long long r;
    asm("mov.b64 %0, {%1, %1};" : "=l"(r) : "f"(v));
    return r;
}
__device__ __forceinline__ void fma2(unsigned long long& acc, unsigned long long a,
                                     unsigned long long b) {
    asm("fma.rn.f32x2 %0, %1, %2, %0;" : "+l"(acc) : "l"(a), "l"(b));
}
__device__ __forceinline__ void unpk2(unsigned long long v, float& lo, float& hi) {
    asm("mov.b64 {%0, %1}, %2;" : "=f"(lo), "=f"(hi) : "l"(v));
}

// -------- K0: zero the small reduction buffers (graph-replay safe) --------
__global__ void k0_zero() {
    int i = blockIdx.x * blockDim.x + threadIdx.x;
    if (i < B_*E_) { d_sumg[i] = 0.0f; d_cnt1[i] = 0; }
}

// -------- per-token top2 + softmax + gate output (group of 4 lanes) --------
__device__ __forceinline__ void do_token(float v[16], int g, int b, int tok,
                                         float ls[16]) {
    // local top-2 over this thread's 16 experts (ascending index => first-occurrence)
    float m1 = -1e30f, m2 = -1e30f; int i1 = 0, i2 = 0;
#pragma unroll
    for (int j = 0; j < 16; j++) {
        int e = (g << 2) + ((j >> 2) << 4) + (j & 3);
        float val = v[j];
        if (val > m1)      { m2 = m1; i2 = i1; m1 = val; i1 = e; }
        else if (val > m2) { m2 = val; i2 = e; }
    }
    // merge across 4 lanes of the expert group
#pragma unroll
    for (int d = 1; d <= 2; d <<= 1) {
        float om1 = __shfl_xor_sync(0xffffffffu, m1, d);
        int   oi1 = __shfl_xor_sync(0xffffffffu, i1, d);
        float om2 = __shfl_xor_sync(0xffffffffu, m2, d);
        int   oi2 = __shfl_xor_sync(0xffffffffu, i2, d);
        if (om1 > m1 || (om1 == m1 && oi1 < i1)) {
            float c = m1; int ci = i1;
            m1 = om1; i1 = oi1;
            if (om2 > c || (om2 == c && oi2 < ci)) { m2 = om2; i2 = oi2; }
            else                                   { m2 = c;   i2 = ci;  }
        } else {
            if (om1 > m2 || (om1 == m2 && oi1 < i2)) { m2 = om1; i2 = oi1; }
        }
    }
    // softmax partition function (group sum)
    float s = 0.0f;
#pragma unroll
    for (int j = 0; j < 16; j++) { v[j] = __expf(v[j] - m1); s += v[j]; }
    s += __shfl_xor_sync(0xffffffffu, s, 1);
    s += __shfl_xor_sync(0xffffffffu, s, 2);
    float invZ = 1.0f / s;
#pragma unroll
    for (int j = 0; j < 16; j++) ls[j] += v[j] * invZ;

    if (g == 0) {
        float e2v = __expf(m2 - m1);
        float den = 1.0f + e2v + 1e-9f * s;   // = (p1+p2+eps)*Z
        float g1 = 1.0f / den, g2 = e2v / den;
        d_g1[tok] = g1;  d_g2[tok] = g2;
        d_i1[tok] = i1;  d_i2[tok] = i2;
        d_keep2[tok] = (g2 > 0.2f) ? 1 : 0;
        atomicAdd(&d_cnt1[(b << 6) + i1], 1);
    }
}

// -------- K1: fused GEMM (f32x2) + softmax/top2 + output zero-fill --------
#define TPB1 128
#define KC   64
#define TOKB 64    // tokens per block
__global__ __launch_bounds__(TPB1) void k1_gate(const float* __restrict__ x,
                                                const float* __restrict__ W,
                                                float* __restrict__ out) {
    __shared__ float sx[TOKB][KC + 1];   // pad 1 -> conflict-free scalar reads
    __shared__ float sw[KC][E_];

    const int tid  = threadIdx.x;
    const int g    = tid & 3;            // expert group: experts g*4 + 16i + s
    const int p    = tid >> 2;           // token pair id 0..31
    const int tok0 = blockIdx.x * TOKB;
    const int tokA = tok0 + 2*p;
    const int tokB = tokA + 1;
    const int b    = tok0 >> 11;

    unsigned long long accA[8], accB[8];
#pragma unroll
    for (int j = 0; j < 8; j++) { accA[j] = 0ULL; accB[j] = 0ULL; }

    // output zero-fill bases (float4 units); block owns 64 tokens * 4096 floats per tensor
    float4* outv = (float4*)out;
    const long long dispB4 = (long long)tok0 * (E_*CAP_/4);
    const long long combB4 = (DTOT_/4) + dispB4;
    const float4 z4 = make_float4(0.f, 0.f, 0.f, 0.f);

    for (int c = 0; c < D_/KC; c++) {
        const int kc = c * KC;
        // load W chunk: 4096 floats = 1024 float4, contiguous
        {
            const float4* wg = (const float4*)(W + kc * E_);
            float4* ws = (float4*)&sw[0][0];
#pragma unroll
            for (int i = 0; i < 8; i++) ws[tid + i*TPB1] = wg[tid + i*TPB1];
        }
        // load x chunk: 64 rows x 64 floats, coalesced float4 loads
        {
#pragma unroll
            for (int i = 0; i < 8; i++) {
                int f = tid + i*TPB1;
                int r = f >> 4;            // 16 float4 per row
                int cc = (f & 15) * 4;
                float4 v = *(const float4*)(x + (size_t)(tok0 + r)*D_ + kc + cc);
                float* dst = &sx[r][cc];
                dst[0]=v.x; dst[1]=v.y; dst[2]=v.z; dst[3]=v.w;
            }
        }
        __syncthreads();

#pragma unroll 4
        for (int kk = 0; kk < KC; kk++) {
            unsigned long long xpA = pk2(sx[2*p][kk]);
            unsigned long long xpB = pk2(sx[2*p+1][kk]);
            const ulonglong2* wp = (const ulonglong2*)&sw[kk][g*4];
            // loads at float offsets g*4 + {0,16,32,48}: 4 distinct 16B chunks
            ulonglong2 w0 = wp[0];   // experts g*4+0..3
            ulonglong2 w1 = wp[4];   // +16 floats = 4 ulonglong2
            ulonglong2 w2 = wp[8];
            ulonglong2 w3 = wp[12];
            fma2(accA[0], xpA, w0.x); fma2(accA[1], xpA, w0.y);
            fma2(accA[2], xpA, w1.x); fma2(accA[3], xpA, w1.y);
            fma2(accA[4], xpA, w2.x); fma2(accA[5], xpA, w2.y);
            fma2(accA[6], xpA, w3.x); fma2(accA[7], xpA, w3.y);
            fma2(accB[0], xpB, w0.x); fma2(accB[1], xpB, w0.y);
            fma2(accB[2], xpB, w1.x); fma2(accB[3], xpB, w1.y);
            fma2(accB[4], xpB, w2.x); fma2(accB[5], xpB, w2.y);
            fma2(accB[6], xpB, w3.x); fma2(accB[7], xpB, w3.y);
        }

        // zero-fill 1/16 of the block's output region (fire-and-forget stores)
        {
            long long base = (c < 8) ? (dispB4 + (long long)c * 8192)
                                     : (combB4 + (long long)(c - 8) * 8192);
#pragma unroll
            for (int j = 0; j < 64; j++) outv[base + tid + j*TPB1] = z4;
        }
        __syncthreads();
    }

    // unpack accumulators; v[4i+s] = expert g*4+16i+s
    float vA[16], vB[16], ls[16];
#pragma unroll
    for (int j = 0; j < 8; j++) {
        unpk2(accA[j], vA[2*j], vA[2*j+1]);
        unpk2(accB[j], vB[2*j], vB[2*j+1]);
    }
#pragma unroll
    for (int j = 0; j < 16; j++) ls[j] = 0.0f;

    do_token(vA, g, b, tokA, ls);
    do_token(vB, g, b, tokB, ls);

    // loss partial: sum per-expert probs over the warp's 16 tokens
#pragma unroll
    for (int j = 0; j < 16; j++) {
        float t = ls[j];
        t += __shfl_xor_sync(0xffffffffu, t, 4);
        t += __shfl_xor_sync(0xffffffffu, t, 8);
        t += __shfl_xor_sync(0xffffffffu, t, 16);
        if ((tid & 31) < 4) {
            int e = (g << 2) + ((j >> 2) << 4) + (j & 3);
            atomicAdd(&d_sumg[(b << 6) + e], t);
        }
    }
}

// -------- K2: capacity scan (warp-parallel prefix counting per batch) --------
__global__ __launch_bounds__(32) void k2_scan() {
    const int b    = blockIdx.x;
    const int lane = threadIdx.x;
    __shared__ int s_cnt[E_];
    __shared__ int s_m1[E_];

    s_cnt[lane] = 0; s_cnt[lane + 32] = 0;
    __syncwarp();

    const int base = b * N_;

    for (int c = 0; c < N_/32; c++) {
        int t  = base + c*32 + lane;
        int i1 = d_i1[t];
        unsigned grp = __match_any_sync(0xffffffffu, i1);
        int before = __popc(grp & ((1u << lane) - 1u));
        int cnt = s_cnt[i1];
        __syncwarp();
        int pos = cnt + before;
        d_pos1[t]  = pos;
        d_keep1[t] = (pos < CAP_) ? 1 : 0;
        int leader = __ffs(grp) - 1;
        if (lane == leader) s_cnt[i1] = cnt + __popc(grp);
        __syncwarp();
    }

    s_m1[lane]      = min(s_cnt[lane], CAP_);
    s_m1[lane + 32] = min(s_cnt[lane + 32], CAP_);
    __syncwarp();
    s_cnt[lane] = 0; s_cnt[lane + 32] = 0;
    __syncwarp();

    for (int c = 0; c < N_/32; c++) {
        int t  = base + c*32 + lane;
        int i2 = d_i2[t];
        int kp = d_keep2[t];
        unsigned kmask = __ballot_sync(0xffffffffu, kp);
        unsigned grp   = __match_any_sync(0xffffffffu, i2) & kmask;
        int before = __popc(grp & ((1u << lane) - 1u));
        int cnt = s_cnt[i2];
        int m1v = s_m1[i2];
        __syncwarp();
        if (kp) {
            int pos = cnt + before + m1v;
            d_pos2[t]  = pos;
            d_keep2[t] = (pos < CAP_) ? 1 : 0;
            int leader = __ffs(grp) - 1;
            if (lane == leader) s_cnt[i2] = cnt + __popc(grp);
        }
        __syncwarp();
    }
}

// -------- K3b: scatter nonzeros (runs after zero-fill in K1 and scan in K2) --
__global__ __launch_bounds__(256) void k3b_scatter(float* __restrict__ out) {
    const int tok = blockIdx.x * blockDim.x + threadIdx.x;   // 16384 threads
    const long long baseD = (long long)tok * (E_ * CAP_);
    if (d_keep1[tok]) {
        int t = d_i1[tok]*CAP_ + d_pos1[tok];
        out[baseD + t]         = 1.0f;
        out[DTOT_ + baseD + t] = d_g1[tok];
    }
    if (d_keep2[tok]) {
        int t = d_i2[tok]*CAP_ + d_pos2[tok];
        out[baseD + t]         = 1.0f;
        out[DTOT_ + baseD + t] = d_g2[tok];
    }
}

// -------- K4: loss finalize --------
__global__ __launch_bounds__(512) void k4_loss(float* __restrict__ out, long long out_size) {
    __shared__ float red[16];
    const int i = threadIdx.x;          // 512 = B_*E_
    float v = d_sumg[i] * (float)d_cnt1[i];
    v += __shfl_xor_sync(0xffffffffu, v, 16);
    v += __shfl_xor_sync(0xffffffffu, v, 8);
    v += __shfl_xor_sync(0xffffffffu, v, 4);
    v += __shfl_xor_sync(0xffffffffu, v, 2);
    v += __shfl_xor_sync(0xffffffffu, v, 1);
    if ((i & 31) == 0) red[i >> 5] = v;
    __syncthreads();
    if (i == 0) {
        float s = 0.0f;
        for (int w = 0; w < 16; w++) s += red[w];
        float loss = s * (8.0f / ((float)N_ * (float)N_));
        if (out_size > 2*DTOT_) out[2*DTOT_] = loss;
    }
}

extern "C" void kernel_launch(void* const* d_in, const int* in_sizes, int n_in,
                              void* d_out, int out_size) {
    const float* x = (const float*)d_in[0];
    const float* W = (const float*)d_in[1];
    float* out = (float*)d_out;

    k0_zero<<<1, 512>>>();
    k1_gate<<<TOK_/TOKB, TPB1>>>(x, W, out);     // 256 blocks x 128 threads
    k2_scan<<<B_, 32>>>();                       // 8 warps, one per batch
    k3b_scatter<<<TOK_/256, 256>>>(out);         // 64 blocks
    k4_loss<<<1, 512>>>(out, (long long)out_size);
}

// round 6
// speedup vs baseline: 1.4098x; 1.2584x over previous
#include <cuda_runtime.h>
#include <cstdint>

#define B_  8
#define N_  2048
#define D_  1024
#define E_  64
#define CAP_ 64
#define TOK_ (B_*N_)                     // 16384
#define DTOT_ ((long long)TOK_*E_*CAP_)  // 67108864

#define GEMMB 256      // GEMM blocks in K1
#define FILLB 1024     // zero-fill blocks in K1

// -------- scratch (device globals; no allocation allowed) --------
__device__ float d_g1[TOK_], d_g2[TOK_];
__device__ int   d_i1[TOK_], d_i2[TOK_];
__device__ int   d_keep2[TOK_];
__device__ float d_sumg[B_*E_];
__device__ int   d_cnt1[B_*E_];

// -------- packed f32x2 helpers --------
__device__ __forceinline__ unsigned long long pk2(float v) {
    unsigned long long r;
    asm("mov.b64 %0, {%1, %1};" : "=l"(r) : "f"(v));
    return r;
}
__device__ __forceinline__ void fma2(unsigned long long& acc, unsigned long long a,
                                     unsigned long long b) {
    asm("fma.rn.f32x2 %0, %1, %2, %0;" : "+l"(acc) : "l"(a), "l"(b));
}
__device__ __forceinline__ void unpk2(unsigned long long v, float& lo, float& hi) {
    asm("mov.b64 {%0, %1}, %2;" : "=f"(lo), "=f"(hi) : "l"(v));
}

// -------- per-token top2 + softmax + gate output (group of 4 lanes) --------
__device__ __forceinline__ void do_token(float v[16], int g, int b, int tok,
                                         float ls[16]) {
    float m1 = -1e30f, m2 = -1e30f; int i1 = 0, i2 = 0;
#pragma unroll
    for (int j = 0; j < 16; j++) {
        int e = (g << 2) + ((j >> 2) << 4) + (j & 3);
        float val = v[j];
        if (val > m1)      { m2 = m1; i2 = i1; m1 = val; i1 = e; }
        else if (val > m2) { m2 = val; i2 = e; }
    }
#pragma unroll
    for (int d = 1; d <= 2; d <<= 1) {
        float om1 = __shfl_xor_sync(0xffffffffu, m1, d);
        int   oi1 = __shfl_xor_sync(0xffffffffu, i1, d);
        float om2 = __shfl_xor_sync(0xffffffffu, m2, d);
        int   oi2 = __shfl_xor_sync(0xffffffffu, i2, d);
        if (om1 > m1 || (om1 == m1 && oi1 < i1)) {
            float c = m1; int ci = i1;
            m1 = om1; i1 = oi1;
            if (om2 > c || (om2 == c && oi2 < ci)) { m2 = om2; i2 = oi2; }
            else                                   { m2 = c;   i2 = ci;  }
        } else {
            if (om1 > m2 || (om1 == m2 && oi1 < i2)) { m2 = om1; i2 = oi1; }
        }
    }
    float s = 0.0f;
#pragma unroll
    for (int j = 0; j < 16; j++) { v[j] = __expf(v[j] - m1); s += v[j]; }
    s += __shfl_xor_sync(0xffffffffu, s, 1);
    s += __shfl_xor_sync(0xffffffffu, s, 2);
    float invZ = 1.0f / s;
#pragma unroll
    for (int j = 0; j < 16; j++) ls[j] += v[j] * invZ;

    if (g == 0) {
        float e2v = __expf(m2 - m1);
        float den = 1.0f + e2v + 1e-9f * s;
        float g1 = 1.0f / den, g2 = e2v / den;
        d_g1[tok] = g1;  d_g2[tok] = g2;
        d_i1[tok] = i1;  d_i2[tok] = i2;
        d_keep2[tok] = (g2 > 0.2f) ? 1 : 0;
        atomicAdd(&d_cnt1[(b << 6) + i1], 1);
    }
}

// -------- K1: role-split launch: 256 GEMM blocks + 1024 zero-fill blocks ----
#define TPB1 128
#define KC   64
#define TOKB 64
__global__ __launch_bounds__(TPB1) void k1_gate_fill(const float* __restrict__ x,
                                                     const float* __restrict__ W,
                                                     float* __restrict__ out) {
    const int tid = threadIdx.x;

    if (blockIdx.x >= GEMMB) {
        // ---------------- fill role: stream 512KB of zeros ----------------
        const long long fb = blockIdx.x - GEMMB;
        float4* outv = (float4*)out;
        const long long base = fb * (long long)(TPB1 * 256);
        const float4 z4 = make_float4(0.f, 0.f, 0.f, 0.f);
#pragma unroll 8
        for (int j = 0; j < 256; j++)
            outv[base + tid + (long long)j * TPB1] = z4;
        return;
    }

    // ---------------- GEMM role ----------------
    __shared__ float sx[TOKB][KC + 1];
    __shared__ float sw[KC][E_];

    const int g    = tid & 3;            // expert group: experts g*4 + 16i + s
    const int p    = tid >> 2;           // token pair id 0..31
    const int tok0 = blockIdx.x * TOKB;
    const int tokA = tok0 + 2*p;
    const int tokB = tokA + 1;
    const int b    = tok0 >> 11;

    unsigned long long accA[8], accB[8];
#pragma unroll
    for (int j = 0; j < 8; j++) { accA[j] = 0ULL; accB[j] = 0ULL; }

    for (int c = 0; c < D_/KC; c++) {
        const int kc = c * KC;
        // W chunk: KC*E_ = 4096 floats = 1024 float4, 8 per thread (coalesced)
        {
            const float4* wg = (const float4*)(W + kc * E_);
            float4* ws = (float4*)&sw[0][0];
#pragma unroll
            for (int i = 0; i < 8; i++) ws[tid + i*TPB1] = wg[tid + i*TPB1];
        }
        // x chunk: 64 rows x 64 floats = 1024 float4 -> 8 iterations (ALL rows!)
        {
#pragma unroll
            for (int i = 0; i < 8; i++) {
                int f = tid + i*TPB1;
                int r = f >> 4;            // 16 float4 per row -> r in 0..63
                int cc = (f & 15) * 4;
                float4 v = *(const float4*)(x + (size_t)(tok0 + r)*D_ + kc + cc);
                float* dst = &sx[r][cc];
                dst[0]=v.x; dst[1]=v.y; dst[2]=v.z; dst[3]=v.w;
            }
        }
        __syncthreads();

#pragma unroll 4
        for (int kk = 0; kk < KC; kk++) {
            unsigned long long xpA = pk2(sx[2*p][kk]);
            unsigned long long xpB = pk2(sx[2*p+1][kk]);
            const ulonglong2* wp = (const ulonglong2*)&sw[kk][g*4];
            ulonglong2 w0 = wp[0];
            ulonglong2 w1 = wp[4];
            ulonglong2 w2 = wp[8];
            ulonglong2 w3 = wp[12];
            fma2(accA[0], xpA, w0.x); fma2(accA[1], xpA, w0.y);
            fma2(accA[2], xpA, w1.x); fma2(accA[3], xpA, w1.y);
            fma2(accA[4], xpA, w2.x); fma2(accA[5], xpA, w2.y);
            fma2(accA[6], xpA, w3.x); fma2(accA[7], xpA, w3.y);
            fma2(accB[0], xpB, w0.x); fma2(accB[1], xpB, w0.y);
            fma2(accB[2], xpB, w1.x); fma2(accB[3], xpB, w1.y);
            fma2(accB[4], xpB, w2.x); fma2(accB[5], xpB, w2.y);
            fma2(accB[6], xpB, w3.x); fma2(accB[7], xpB, w3.y);
        }
        __syncthreads();
    }

    float vA[16], vB[16], ls[16];
#pragma unroll
    for (int j = 0; j < 8; j++) {
        unpk2(accA[j], vA[2*j], vA[2*j+1]);
        unpk2(accB[j], vB[2*j], vB[2*j+1]);
    }
#pragma unroll
    for (int j = 0; j < 16; j++) ls[j] = 0.0f;

    do_token(vA, g, b, tokA, ls);
    do_token(vB, g, b, tokB, ls);

#pragma unroll
    for (int j = 0; j < 16; j++) {
        float t = ls[j];
        t += __shfl_xor_sync(0xffffffffu, t, 4);
        t += __shfl_xor_sync(0xffffffffu, t, 8);
        t += __shfl_xor_sync(0xffffffffu, t, 16);
        if ((tid & 31) < 4) {
            int e = (g << 2) + ((j >> 2) << 4) + (j & 3);
            atomicAdd(&d_sumg[(b << 6) + e], t);
        }
    }
}

// -------- K2: parallel capacity scan + scatter (8 warps per batch) ---------
__global__ __launch_bounds__(256) void k2_scan_scatter(float* __restrict__ out) {
    const int b    = blockIdx.x;
    const int tid  = threadIdx.x;
    const int w    = tid >> 5;
    const int lane = tid & 31;
    const unsigned lt = (1u << lane) - 1u;

    __shared__ int cnt[8][E_];
    __shared__ int pre[8][E_];
    __shared__ int m1c[E_];

    for (int i = tid; i < 8*E_; i += 256) ((int*)cnt)[i] = 0;
    __syncthreads();

    const int base = b * N_ + w * 256;

    // ---- pass 1: top-1 ----
    int i1v[8], lp1[8];
#pragma unroll
    for (int c = 0; c < 8; c++) {
        int t  = base + c*32 + lane;
        int i1 = d_i1[t];
        i1v[c] = i1;
        unsigned grp = __match_any_sync(0xffffffffu, i1);
        int before = __popc(grp & lt);
        int cv = cnt[w][i1];
        __syncwarp();
        lp1[c] = cv + before;
        if (lane == __ffs(grp) - 1) cnt[w][i1] = cv + __popc(grp);
        __syncwarp();
    }
    __syncthreads();

    // prefix over warps per expert; mask_1_count (count AFTER capacity cap)
    if (tid < E_) {
        int s = 0;
#pragma unroll
        for (int ww = 0; ww < 8; ww++) { pre[ww][tid] = s; s += cnt[ww][tid]; }
        m1c[tid] = min(s, CAP_);
    }
    __syncthreads();

#pragma unroll
    for (int c = 0; c < 8; c++) {
        int t   = base + c*32 + lane;
        int pos = lp1[c] + pre[w][i1v[c]];
        if (pos < CAP_) {
            long long baseD = (long long)t * (E_*CAP_);
            int o = i1v[c]*CAP_ + pos;
            out[baseD + o]         = 1.0f;
            out[DTOT_ + baseD + o] = d_g1[t];
        }
    }
    __syncthreads();

    // ---- pass 2: top-2 (thresholded), offset by mask_1_count ----
    for (int i = tid; i < 8*E_; i += 256) ((int*)cnt)[i] = 0;
    __syncthreads();

    int i2v[8], lp2[8], kp2[8];
#pragma unroll
    for (int c = 0; c < 8; c++) {
        int t  = base + c*32 + lane;
        int i2 = d_i2[t];
        int kp = d_keep2[t];
        i2v[c] = i2; kp2[c] = kp;
        unsigned km  = __ballot_sync(0xffffffffu, kp);
        unsigned grp = __match_any_sync(0xffffffffu, i2) & km;
        int before = __popc(grp & lt);
        int cv = cnt[w][i2];
        __syncwarp();
        lp2[c] = cv + before;
        if (kp && lane == __ffs(grp) - 1) cnt[w][i2] = cv + __popc(grp);
        __syncwarp();
    }
    __syncthreads();

    if (tid < E_) {
        int s = 0;
#pragma unroll
        for (int ww = 0; ww < 8; ww++) { pre[ww][tid] = s; s += cnt[ww][tid]; }
    }
    __syncthreads();

#pragma unroll
    for (int c = 0; c < 8; c++) {
        if (!kp2[c]) continue;
        int t   = base + c*32 + lane;
        int e   = i2v[c];
        int pos = lp2[c] + pre[w][e] + m1c[e];
        if (pos < CAP_) {
            long long baseD = (long long)t * (E_*CAP_);
            int o = e*CAP_ + pos;
            out[baseD + o]         = 1.0f;
            out[DTOT_ + baseD + o] = d_g2[t];
        }
    }
}

// -------- K4: loss finalize + scratch re-zero for next graph replay --------
__global__ __launch_bounds__(512) void k4_loss(float* __restrict__ out, long long out_size) {
    __shared__ float red[16];
    const int i = threadIdx.x;          // 512 = B_*E_
    float v = d_sumg[i] * (float)d_cnt1[i];
    v += __shfl_xor_sync(0xffffffffu, v, 16);
    v += __shfl_xor_sync(0xffffffffu, v, 8);
    v += __shfl_xor_sync(0xffffffffu, v, 4);
    v += __shfl_xor_sync(0xffffffffu, v, 2);
    v += __shfl_xor_sync(0xffffffffu, v, 1);
    if ((i & 31) == 0) red[i >> 5] = v;
    // restore scratch to zero so every graph replay sees identical state
    d_sumg[i] = 0.0f;
    d_cnt1[i] = 0;
    __syncthreads();
    if (i == 0) {
        float s = 0.0f;
        for (int w = 0; w < 16; w++) s += red[w];
        float loss = s * (8.0f / ((float)N_ * (float)N_));
        if (out_size > 2*DTOT_) out[2*DTOT_] = loss;
    }
}

extern "C" void kernel_launch(void* const* d_in, const int* in_sizes, int n_in,
                              void* d_out, int out_size) {
    const float* x = (const float*)d_in[0];
    const float* W = (const float*)d_in[1];
    float* out = (float*)d_out;

    k1_gate_fill<<<GEMMB + FILLB, TPB1>>>(x, W, out);  // 1280 blocks
    k2_scan_scatter<<<B_, 256>>>(out);                 // 8 blocks
    k4_loss<<<1, 512>>>(out, (long long)out_size);
}